// round 1
// baseline (speedup 1.0000x reference)
#include <cuda_runtime.h>

#define NMAX   200000
#define HDIM   64
#define CDIM   128
#define KEEPK  63

// 51.2 MB device scratch for the intermediate f = elu(elu(x+y)@Wa)  [N,64]
__device__ float g_f[(size_t)NMAX * HDIM];

typedef unsigned long long u64;

__device__ __forceinline__ void ffma2(u64 &acc, u64 a, u64 b) {
    asm("fma.rn.f32x2 %0, %1, %2, %0;" : "+l"(acc) : "l"(a), "l"(b));
}
__device__ __forceinline__ float pairsum(u64 v) {
    return __uint_as_float((unsigned)v) + __uint_as_float((unsigned)(v >> 32));
}
__device__ __forceinline__ float eluf(float v) {
    return v > 0.f ? v : expm1f(v);
}

// ---------------------------------------------------------------------------
// Kernel 1: f = elu( elu(x+y) @ Wa )    [N,128] @ [128,64] -> [N,64]
// Block: 256 threads, 128 rows. Wa repacked pair-major (d-pairs) in smem.
// ---------------------------------------------------------------------------
#define K1_ROWS   128
#define SA_STRIDE 132   // 128 + 4: float4-aligned, rg-groups (4 rows apart) hit distinct banks

__global__ __launch_bounds__(256, 1)
void k1_kernel(const float* __restrict__ x, const float* __restrict__ y,
               const float* __restrict__ Wa, int N)
{
    extern __shared__ float sm[];
    float* sWa = sm;            // 64 dp * 128  = 8192 floats (pair-major Wa)
    float* sA  = sm + 8192;     // 128 * 132    = 16896 floats

    int tid = threadIdx.x;
    int r0  = blockIdx.x * K1_ROWS;

    // repack Wa[d][c] -> word (d>>1)*128 + 2c + (d&1)
    for (int j = tid; j < 2048; j += 256) {
        int d = j >> 4, c0 = (j & 15) * 4;
        float4 w = *(const float4*)&Wa[d * 64 + c0];
        int base = (d >> 1) * 128 + (d & 1);
        sWa[base + 2 * (c0 + 0)] = w.x;
        sWa[base + 2 * (c0 + 1)] = w.y;
        sWa[base + 2 * (c0 + 2)] = w.z;
        sWa[base + 2 * (c0 + 3)] = w.w;
    }
    // input tile: elu(x+y)
    for (int j = tid; j < 4096; j += 256) {
        int r = j >> 5, c0 = (j & 31) * 4;
        int gr = r0 + r;
        float4 v = make_float4(0.f, 0.f, 0.f, 0.f);
        if (gr < N) {
            float4 xv = *(const float4*)&x[(size_t)gr * CDIM + c0];
            float4 yv = *(const float4*)&y[(size_t)gr * CDIM + c0];
            v.x = eluf(xv.x + yv.x); v.y = eluf(xv.y + yv.y);
            v.z = eluf(xv.z + yv.z); v.w = eluf(xv.w + yv.w);
        }
        *(float4*)&sA[r * SA_STRIDE + c0] = v;
    }
    __syncthreads();

    int wid = tid >> 5, lane = tid & 31;
    int cg = lane & 15, rg = lane >> 4;
    // lane owns channels {2cg, 2cg+1, 2cg+32, 2cg+33}, rows rbase..rbase+3

    for (int g = wid; g < 16; g += 8) {
        int rbase = g * 8 + rg * 4;
        u64 acc[4][4];
        #pragma unroll
        for (int i = 0; i < 4; i++)
            #pragma unroll
            for (int j = 0; j < 4; j++) acc[i][j] = 0ull;

        #pragma unroll 8
        for (int dp = 0; dp < 64; dp++) {
            u64 a_[4];
            #pragma unroll
            for (int i = 0; i < 4; i++)
                a_[i] = *(const u64*)&sA[(rbase + i) * SA_STRIDE + 2 * dp];
            ulonglong2 w0 = *(const ulonglong2*)&sWa[dp * 128 + 4 * cg];
            ulonglong2 w1 = *(const ulonglong2*)&sWa[dp * 128 + 64 + 4 * cg];
            #pragma unroll
            for (int i = 0; i < 4; i++) {
                ffma2(acc[i][0], a_[i], w0.x);
                ffma2(acc[i][1], a_[i], w0.y);
                ffma2(acc[i][2], a_[i], w1.x);
                ffma2(acc[i][3], a_[i], w1.y);
            }
        }
        #pragma unroll
        for (int i = 0; i < 4; i++) {
            int grow = r0 + rbase + i;
            if (grow < N) {
                float2 v0, v1;
                v0.x = eluf(pairsum(acc[i][0]));
                v0.y = eluf(pairsum(acc[i][1]));
                v1.x = eluf(pairsum(acc[i][2]));
                v1.y = eluf(pairsum(acc[i][3]));
                *(float2*)&g_f[(size_t)grow * HDIM + 2 * cg]      = v0;
                *(float2*)&g_f[(size_t)grow * HDIM + 2 * cg + 32] = v1;
            }
        }
    }
}

// ---------------------------------------------------------------------------
// Kernel 2: sparse conv over 63 offsets (compacted valid rows), then
// out = x + elu(acc) @ Wc.   Block: 256 threads, 256 rows.
// ---------------------------------------------------------------------------
#define M_TILE    256
#define FB_STRIDE 68    // float4-aligned; rows 4 apart differ by 16 banks

__global__ __launch_bounds__(256, 1)
void k2_kernel(const float* __restrict__ Wb, const float* __restrict__ Wc,
               const int* __restrict__ nidx, const float* __restrict__ x,
               float* __restrict__ out, int N)
{
    extern __shared__ float sm[];
    float* accS = sm;              // 256*64  = 16384
    float* sWb  = sm + 16384;      // 32*128  = 4096   (pair-major Wb[k])
    float* sWc  = sm + 20480;      // 32*256  = 8192   (pair-major Wc)
    float* fbuf = sm + 28672;      // 64*68   = 4352
    __shared__ int s_gidx[256];
    __shared__ int s_row[256];
    __shared__ int s_cnt;

    int tid  = threadIdx.x;
    int wid  = tid >> 5, lane = tid & 31;
    int cg   = lane & 15, rg = lane >> 4;
    int r0   = blockIdx.x * M_TILE;

    // repack Wc[d][c] (64x128) -> word (d>>1)*256 + 2c + (d&1)
    for (int j = tid; j < 2048; j += 256) {
        int d = j >> 5, c0 = (j & 31) * 4;
        float4 w = *(const float4*)&Wc[d * 128 + c0];
        int base = (d >> 1) * 256 + (d & 1);
        sWc[base + 2 * (c0 + 0)] = w.x;
        sWc[base + 2 * (c0 + 1)] = w.y;
        sWc[base + 2 * (c0 + 2)] = w.z;
        sWc[base + 2 * (c0 + 3)] = w.w;
    }
    for (int j = tid * 4; j < 16384; j += 1024)
        *(float4*)&accS[j] = make_float4(0.f, 0.f, 0.f, 0.f);
    __syncthreads();

    for (int k = 0; k < KEEPK; k++) {
        if (tid == 0) s_cnt = 0;
        // repack Wb[k][d][c] (64x64) -> word (d>>1)*128 + 2c + (d&1)
        for (int j = tid; j < 1024; j += 256) {
            int d = j >> 4, c0 = (j & 15) * 4;
            float4 w = *(const float4*)&Wb[(size_t)k * 4096 + d * 64 + c0];
            int base = (d >> 1) * 128 + (d & 1);
            sWb[base + 2 * (c0 + 0)] = w.x;
            sWb[base + 2 * (c0 + 1)] = w.y;
            sWb[base + 2 * (c0 + 2)] = w.z;
            sWb[base + 2 * (c0 + 3)] = w.w;
        }
        __syncthreads();

        // compact valid rows for this offset
        {
            int r = r0 + tid;
            if (r < N) {
                int idx = nidx[(size_t)k * N + r];
                if (idx >= 0) {
                    int p = atomicAdd(&s_cnt, 1);
                    s_gidx[p] = idx;
                    s_row[p]  = tid;
                }
            }
        }
        __syncthreads();
        int V = s_cnt;

        for (int v0 = 0; v0 < V; v0 += 64) {
            int VC    = min(64, V - v0);
            int VCpad = (VC + 7) & ~7;
            // gather rows of f into fbuf (zero-pad to group multiple)
            for (int j = tid; j < VCpad * 16; j += 256) {
                int v = j >> 4, q = (j & 15) * 4;
                float4 val = make_float4(0.f, 0.f, 0.f, 0.f);
                if (v < VC)
                    val = *(const float4*)&g_f[(size_t)s_gidx[v0 + v] * HDIM + q];
                *(float4*)&fbuf[v * FB_STRIDE + q] = val;
            }
            __syncthreads();

            int ngroups = VCpad >> 3;
            if (wid < ngroups) {
                int vb = wid * 8 + rg * 4;
                u64 acc[4][4];
                #pragma unroll
                for (int i = 0; i < 4; i++)
                    #pragma unroll
                    for (int j = 0; j < 4; j++) acc[i][j] = 0ull;

                #pragma unroll
                for (int dp = 0; dp < 32; dp++) {
                    u64 a_[4];
                    #pragma unroll
                    for (int i = 0; i < 4; i++)
                        a_[i] = *(const u64*)&fbuf[(vb + i) * FB_STRIDE + 2 * dp];
                    ulonglong2 w0 = *(const ulonglong2*)&sWb[dp * 128 + 4 * cg];
                    ulonglong2 w1 = *(const ulonglong2*)&sWb[dp * 128 + 64 + 4 * cg];
                    #pragma unroll
                    for (int i = 0; i < 4; i++) {
                        ffma2(acc[i][0], a_[i], w0.x);
                        ffma2(acc[i][1], a_[i], w0.y);
                        ffma2(acc[i][2], a_[i], w1.x);
                        ffma2(acc[i][3], a_[i], w1.y);
                    }
                }
                #pragma unroll
                for (int i = 0; i < 4; i++) {
                    int v = vb + i;
                    if (v < VC) {
                        int lr = s_row[v0 + v];
                        float2* p0 = (float2*)&accS[lr * 64 + 2 * cg];
                        float2* p1 = (float2*)&accS[lr * 64 + 2 * cg + 32];
                        float2 t0 = *p0, t1 = *p1;
                        t0.x += pairsum(acc[i][0]);
                        t0.y += pairsum(acc[i][1]);
                        t1.x += pairsum(acc[i][2]);
                        t1.y += pairsum(acc[i][3]);
                        *p0 = t0; *p1 = t1;
                    }
                }
            }
            __syncthreads();
        }
    }

    // epilogue: elu in place, then out = x + accS @ Wc
    for (int j = tid; j < 16384; j += 256) accS[j] = eluf(accS[j]);
    __syncthreads();

    // lane owns channels {2l, 2l+1, 2l+64, 2l+65}; group = 4 rows (broadcast a)
    for (int g = wid; g < 64; g += 8) {
        int rbase = g * 4;
        u64 acc[4][4];
        #pragma unroll
        for (int i = 0; i < 4; i++)
            #pragma unroll
            for (int j = 0; j < 4; j++) acc[i][j] = 0ull;

        #pragma unroll
        for (int dp = 0; dp < 32; dp++) {
            u64 a_[4];
            #pragma unroll
            for (int i = 0; i < 4; i++)
                a_[i] = *(const u64*)&accS[(rbase + i) * 64 + 2 * dp];
            ulonglong2 w0 = *(const ulonglong2*)&sWc[dp * 256 + 4 * lane];
            ulonglong2 w1 = *(const ulonglong2*)&sWc[dp * 256 + 128 + 4 * lane];
            #pragma unroll
            for (int i = 0; i < 4; i++) {
                ffma2(acc[i][0], a_[i], w0.x);
                ffma2(acc[i][1], a_[i], w0.y);
                ffma2(acc[i][2], a_[i], w1.x);
                ffma2(acc[i][3], a_[i], w1.y);
            }
        }
        #pragma unroll
        for (int i = 0; i < 4; i++) {
            int grow = r0 + rbase + i;
            if (grow < N) {
                float2 xv0 = *(const float2*)&x[(size_t)grow * CDIM + 2 * lane];
                float2 xv1 = *(const float2*)&x[(size_t)grow * CDIM + 2 * lane + 64];
                float2 o0, o1;
                o0.x = xv0.x + pairsum(acc[i][0]);
                o0.y = xv0.y + pairsum(acc[i][1]);
                o1.x = xv1.x + pairsum(acc[i][2]);
                o1.y = xv1.y + pairsum(acc[i][3]);
                *(float2*)&out[(size_t)grow * CDIM + 2 * lane]      = o0;
                *(float2*)&out[(size_t)grow * CDIM + 2 * lane + 64] = o1;
            }
        }
    }
}

// ---------------------------------------------------------------------------
extern "C" void kernel_launch(void* const* d_in, const int* in_sizes, int n_in,
                              void* d_out, int out_size)
{
    const float* x    = (const float*)d_in[0];
    const float* y    = (const float*)d_in[1];
    const float* Wa   = (const float*)d_in[2];
    const float* Wb   = (const float*)d_in[3];
    const float* Wc   = (const float*)d_in[4];
    const int*   nidx = (const int*)  d_in[5];
    float* out = (float*)d_out;

    int N = in_sizes[0] / CDIM;

    const int SMEM1 = (8192 + 128 * SA_STRIDE) * (int)sizeof(float);          // 100352
    const int SMEM2 = (16384 + 4096 + 8192 + 64 * FB_STRIDE) * (int)sizeof(float); // 132096

    cudaFuncSetAttribute(k1_kernel, cudaFuncAttributeMaxDynamicSharedMemorySize, SMEM1);
    cudaFuncSetAttribute(k2_kernel, cudaFuncAttributeMaxDynamicSharedMemorySize, SMEM2);

    int grid1 = (N + K1_ROWS - 1) / K1_ROWS;
    int grid2 = (N + M_TILE - 1) / M_TILE;

    k1_kernel<<<grid1, 256, SMEM1>>>(x, y, Wa, N);
    k2_kernel<<<grid2, 256, SMEM2>>>(Wb, Wc, nidx, x, out, N);
}

// round 3
// speedup vs baseline: 1.9373x; 1.9373x over previous
#include <cuda_runtime.h>

#define NMAX   200000
#define HDIM   64
#define CDIM   128
#define KEEPK  63
#define MAXTILES (KEEPK * ((NMAX + 63) / 64))

// ---- device scratch (static; no allocation) ------------------------------
__device__ __align__(16) float g_f  [(size_t)NMAX * HDIM];   // 51.2 MB
__device__ __align__(16) float g_acc[(size_t)NMAX * HDIM];   // 51.2 MB
__device__ int2  g_pairs[(size_t)KEEPK * NMAX];              // 100.8 MB
__device__ int   g_cnt[KEEPK];
__device__ int   g_tiles[MAXTILES];
__device__ int   g_ntiles;

typedef unsigned long long u64;

__device__ __forceinline__ void ffma2(u64 &acc, u64 a, u64 b) {
    asm("fma.rn.f32x2 %0, %1, %2, %0;" : "+l"(acc) : "l"(a), "l"(b));
}
__device__ __forceinline__ float pairsum(u64 v) {
    return __uint_as_float((unsigned)v) + __uint_as_float((unsigned)(v >> 32));
}
__device__ __forceinline__ float eluf(float v) {
    return v > 0.f ? v : expm1f(v);
}
__device__ __forceinline__ void red_add_v2(float* p, float a, float b) {
    asm volatile("red.global.add.v2.f32 [%0], {%1, %2};"
                 :: "l"(p), "f"(a), "f"(b) : "memory");
}

// ---------------------------------------------------------------------------
// kZ: zero accumulator + per-offset counters
// ---------------------------------------------------------------------------
__global__ void kz_kernel(int nvec)
{
    float4 z = make_float4(0.f, 0.f, 0.f, 0.f);
    for (int i = blockIdx.x * blockDim.x + threadIdx.x; i < nvec;
         i += gridDim.x * blockDim.x)
        ((float4*)g_acc)[i] = z;
    if (blockIdx.x == 0 && threadIdx.x < KEEPK) g_cnt[threadIdx.x] = 0;
}

// ---------------------------------------------------------------------------
// k1: f = elu( elu(x+y) @ Wa )   [N,128]@[128,64] -> [N,64]
// 256 threads, 64 rows/block, one 8-row group per warp.
// ---------------------------------------------------------------------------
#define SA_STRIDE 132   // 528 B/row: float4-aligned

__global__ __launch_bounds__(256, 2)
void k1_kernel(const float* __restrict__ x, const float* __restrict__ y,
               const float* __restrict__ Wa, int N)
{
    extern __shared__ float sm[];
    float* sWa = sm;            // 64 dp * 128 = 8192 (pair-major Wa)
    float* sA  = sm + 8192;     // 64 * 132    = 8448

    int tid = threadIdx.x;
    int r0  = blockIdx.x * 64;

    // repack Wa[d][c] -> word (d>>1)*128 + 2c + (d&1)
    for (int j = tid; j < 2048; j += 256) {
        int d = j >> 4, c0 = (j & 15) * 4;
        float4 w = *(const float4*)&Wa[d * 64 + c0];
        int base = (d >> 1) * 128 + (d & 1);
        sWa[base + 2 * (c0 + 0)] = w.x;
        sWa[base + 2 * (c0 + 1)] = w.y;
        sWa[base + 2 * (c0 + 2)] = w.z;
        sWa[base + 2 * (c0 + 3)] = w.w;
    }
    // tile: elu(x+y)
    for (int j = tid; j < 2048; j += 256) {
        int r = j >> 5, c0 = (j & 31) * 4;
        int gr = r0 + r;
        float4 v = make_float4(0.f, 0.f, 0.f, 0.f);
        if (gr < N) {
            float4 xv = *(const float4*)&x[(size_t)gr * CDIM + c0];
            float4 yv = *(const float4*)&y[(size_t)gr * CDIM + c0];
            v.x = eluf(xv.x + yv.x); v.y = eluf(xv.y + yv.y);
            v.z = eluf(xv.z + yv.z); v.w = eluf(xv.w + yv.w);
        }
        *(float4*)&sA[r * SA_STRIDE + c0] = v;
    }
    __syncthreads();

    int wid = tid >> 5, lane = tid & 31;
    int cg = lane & 15, rg = lane >> 4;
    int rbase = wid * 8 + rg * 4;

    u64 acc[4][4];
    #pragma unroll
    for (int i = 0; i < 4; i++)
        #pragma unroll
        for (int j = 0; j < 4; j++) acc[i][j] = 0ull;

    #pragma unroll 4
    for (int dp = 0; dp < 64; dp++) {
        u64 a_[4];
        #pragma unroll
        for (int i = 0; i < 4; i++)
            a_[i] = *(const u64*)&sA[(rbase + i) * SA_STRIDE + 2 * dp];
        ulonglong2 w0 = *(const ulonglong2*)&sWa[dp * 128 + 4 * cg];
        ulonglong2 w1 = *(const ulonglong2*)&sWa[dp * 128 + 64 + 4 * cg];
        #pragma unroll
        for (int i = 0; i < 4; i++) {
            ffma2(acc[i][0], a_[i], w0.x);
            ffma2(acc[i][1], a_[i], w0.y);
            ffma2(acc[i][2], a_[i], w1.x);
            ffma2(acc[i][3], a_[i], w1.y);
        }
    }
    #pragma unroll
    for (int i = 0; i < 4; i++) {
        int grow = r0 + rbase + i;
        if (grow < N) {
            float2 v0, v1;
            v0.x = eluf(pairsum(acc[i][0]));
            v0.y = eluf(pairsum(acc[i][1]));
            v1.x = eluf(pairsum(acc[i][2]));
            v1.y = eluf(pairsum(acc[i][3]));
            *(float2*)&g_f[(size_t)grow * HDIM + 2 * cg]      = v0;
            *(float2*)&g_f[(size_t)grow * HDIM + 2 * cg + 32] = v1;
        }
    }
}

// ---------------------------------------------------------------------------
// kA: global compaction. grid = (ceil(N/256), 63). Warp-aggregated atomics.
// ---------------------------------------------------------------------------
__global__ void ka_kernel(const int* __restrict__ nidx, int N)
{
    int k = blockIdx.y;
    int r = blockIdx.x * blockDim.x + threadIdx.x;
    int idx = -1;
    if (r < N) idx = nidx[(size_t)k * N + r];
    bool valid = idx >= 0;
    unsigned m = __ballot_sync(0xffffffffu, valid);
    int lane = threadIdx.x & 31;
    int base = 0;
    if (lane == 0 && m) base = atomicAdd(&g_cnt[k], __popc(m));
    base = __shfl_sync(0xffffffffu, base, 0);
    if (valid) {
        int pos = base + __popc(m & ((1u << lane) - 1));
        g_pairs[(size_t)k * NMAX + pos] = make_int2(r, idx);
    }
}

// ---------------------------------------------------------------------------
// kT: build flat tile list. One block.
// ---------------------------------------------------------------------------
__global__ void kt_kernel()
{
    __shared__ int sbase[KEEPK + 1];
    if (threadIdx.x == 0) {
        int s = 0;
        for (int k = 0; k < KEEPK; k++) {
            sbase[k] = s;
            s += (g_cnt[k] + 63) >> 6;
        }
        sbase[KEEPK] = s;
        g_ntiles = s;
    }
    __syncthreads();
    for (int k = 0; k < KEEPK; k++) {
        int b = sbase[k], nt = sbase[k + 1] - b;
        for (int t = threadIdx.x; t < nt; t += blockDim.x)
            g_tiles[b + t] = (k << 16) | t;
    }
}

// ---------------------------------------------------------------------------
// kB: per-tile gathered GEMM, 64 pairs/tile, 8 warps x 8 rows, scatter via
// red.global.add.v2.f32 into g_acc.
// ---------------------------------------------------------------------------
#define FB_STRIDE 68   // 272 B/row: 16B-aligned rows (u64/float4 safe)

__global__ __launch_bounds__(256, 2)
void kb_kernel(const float* __restrict__ Wb)
{
    extern __shared__ float sm[];
    float* sWb  = sm;                 // 4096 (pair-major Wb[k])
    float* fbuf = sm + 4096;          // 64*68 = 4352
    int* s_orow = (int*)(sm + 8448);  // 64
    int* s_irow = s_orow + 64;        // 64

    int tid = threadIdx.x;
    int wid = tid >> 5, lane = tid & 31;
    int cg = lane & 15, rg = lane >> 4;
    int ntiles = g_ntiles;

    for (int tl = blockIdx.x; tl < ntiles; tl += gridDim.x) {
        int d = g_tiles[tl];
        int k = d >> 16, t = d & 0xffff;
        int cc = min(64, g_cnt[k] - t * 64);
        int p0 = t * 64;

        __syncthreads();   // guard reuse of sWb/fbuf from previous tile

        // repack Wb[k][d][c] -> word (d>>1)*128 + 2c + (d&1)
        for (int j = tid; j < 1024; j += 256) {
            int dd = j >> 4, c0 = (j & 15) * 4;
            float4 w = *(const float4*)&Wb[(size_t)k * 4096 + dd * 64 + c0];
            int base = (dd >> 1) * 128 + (dd & 1);
            sWb[base + 2 * (c0 + 0)] = w.x;
            sWb[base + 2 * (c0 + 1)] = w.y;
            sWb[base + 2 * (c0 + 2)] = w.z;
            sWb[base + 2 * (c0 + 3)] = w.w;
        }
        if (tid < 64) {
            if (tid < cc) {
                int2 pr = g_pairs[(size_t)k * NMAX + p0 + tid];
                s_orow[tid] = pr.x;
                s_irow[tid] = pr.y;
            } else {
                s_orow[tid] = -1;
                s_irow[tid] = 0;
            }
        }
        __syncthreads();

        // gather f rows
        for (int j = tid; j < 1024; j += 256) {
            int v = j >> 4, q = (j & 15) * 4;
            float4 val = make_float4(0.f, 0.f, 0.f, 0.f);
            if (v < cc)
                val = *(const float4*)&g_f[(size_t)s_irow[v] * HDIM + q];
            *(float4*)&fbuf[v * FB_STRIDE + q] = val;
        }
        __syncthreads();

        int vb = wid * 8 + rg * 4;
        u64 acc[4][4];
        #pragma unroll
        for (int i = 0; i < 4; i++)
            #pragma unroll
            for (int j = 0; j < 4; j++) acc[i][j] = 0ull;

        #pragma unroll 4
        for (int dp = 0; dp < 32; dp++) {
            u64 a_[4];
            #pragma unroll
            for (int i = 0; i < 4; i++)
                a_[i] = *(const u64*)&fbuf[(vb + i) * FB_STRIDE + 2 * dp];
            ulonglong2 w0 = *(const ulonglong2*)&sWb[dp * 128 + 4 * cg];
            ulonglong2 w1 = *(const ulonglong2*)&sWb[dp * 128 + 64 + 4 * cg];
            #pragma unroll
            for (int i = 0; i < 4; i++) {
                ffma2(acc[i][0], a_[i], w0.x);
                ffma2(acc[i][1], a_[i], w0.y);
                ffma2(acc[i][2], a_[i], w1.x);
                ffma2(acc[i][3], a_[i], w1.y);
            }
        }
        #pragma unroll
        for (int i = 0; i < 4; i++) {
            int orow = s_orow[vb + i];
            if (orow >= 0) {
                float* p = &g_acc[(size_t)orow * HDIM + 2 * cg];
                red_add_v2(p,      pairsum(acc[i][0]), pairsum(acc[i][1]));
                red_add_v2(p + 32, pairsum(acc[i][2]), pairsum(acc[i][3]));
            }
        }
    }
}

// ---------------------------------------------------------------------------
// k3: out = x + elu(g_acc) @ Wc     [N,64]@[64,128]
// 256 threads, 64 rows/block; warp = 8 rows in 2 chunks of 4.
// ---------------------------------------------------------------------------
#define HS_STRIDE 68   // 272 B/row: 16B-aligned rows

__global__ __launch_bounds__(256, 2)
void k3_kernel(const float* __restrict__ Wc, const float* __restrict__ x,
               float* __restrict__ out, int N)
{
    extern __shared__ float sm[];
    float* sWc = sm;              // 32*256 = 8192 (pair-major Wc)
    float* hS  = sm + 8192;       // 64*68  = 4352

    int tid = threadIdx.x;
    int wid = tid >> 5, lane = tid & 31;
    int r0 = blockIdx.x * 64;

    // repack Wc[d][c] (64x128) -> word (d>>1)*256 + 2c + (d&1)
    for (int j = tid; j < 2048; j += 256) {
        int d = j >> 5, c0 = (j & 31) * 4;
        float4 w = *(const float4*)&Wc[d * 128 + c0];
        int base = (d >> 1) * 256 + (d & 1);
        sWc[base + 2 * (c0 + 0)] = w.x;
        sWc[base + 2 * (c0 + 1)] = w.y;
        sWc[base + 2 * (c0 + 2)] = w.z;
        sWc[base + 2 * (c0 + 3)] = w.w;
    }
    // load accumulator tile + elu
    for (int j = tid; j < 1024; j += 256) {
        int r = j >> 4, q = (j & 15) * 4;
        int gr = r0 + r;
        float4 v = make_float4(0.f, 0.f, 0.f, 0.f);
        if (gr < N) {
            v = *(const float4*)&g_acc[(size_t)gr * HDIM + q];
            v.x = eluf(v.x); v.y = eluf(v.y);
            v.z = eluf(v.z); v.w = eluf(v.w);
        }
        *(float4*)&hS[r * HS_STRIDE + q] = v;
    }
    __syncthreads();

    // lane owns channels {2l, 2l+1, 2l+64, 2l+65}
    #pragma unroll
    for (int h = 0; h < 2; h++) {
        int rbase = wid * 8 + h * 4;
        u64 acc[4][4];
        #pragma unroll
        for (int i = 0; i < 4; i++)
            #pragma unroll
            for (int j = 0; j < 4; j++) acc[i][j] = 0ull;

        #pragma unroll 4
        for (int dp = 0; dp < 32; dp++) {
            u64 a_[4];
            #pragma unroll
            for (int i = 0; i < 4; i++)
                a_[i] = *(const u64*)&hS[(rbase + i) * HS_STRIDE + 2 * dp];
            ulonglong2 w0 = *(const ulonglong2*)&sWc[dp * 256 + 4 * lane];
            ulonglong2 w1 = *(const ulonglong2*)&sWc[dp * 256 + 128 + 4 * lane];
            #pragma unroll
            for (int i = 0; i < 4; i++) {
                ffma2(acc[i][0], a_[i], w0.x);
                ffma2(acc[i][1], a_[i], w0.y);
                ffma2(acc[i][2], a_[i], w1.x);
                ffma2(acc[i][3], a_[i], w1.y);
            }
        }
        #pragma unroll
        for (int i = 0; i < 4; i++) {
            int grow = r0 + rbase + i;
            if (grow < N) {
                float2 xv0 = *(const float2*)&x[(size_t)grow * CDIM + 2 * lane];
                float2 xv1 = *(const float2*)&x[(size_t)grow * CDIM + 2 * lane + 64];
                float2 o0, o1;
                o0.x = xv0.x + pairsum(acc[i][0]);
                o0.y = xv0.y + pairsum(acc[i][1]);
                o1.x = xv1.x + pairsum(acc[i][2]);
                o1.y = xv1.y + pairsum(acc[i][3]);
                *(float2*)&out[(size_t)grow * CDIM + 2 * lane]      = o0;
                *(float2*)&out[(size_t)grow * CDIM + 2 * lane + 64] = o1;
            }
        }
    }
}

// ---------------------------------------------------------------------------
extern "C" void kernel_launch(void* const* d_in, const int* in_sizes, int n_in,
                              void* d_out, int out_size)
{
    const float* x    = (const float*)d_in[0];
    const float* y    = (const float*)d_in[1];
    const float* Wa   = (const float*)d_in[2];
    const float* Wb   = (const float*)d_in[3];
    const float* Wc   = (const float*)d_in[4];
    const int*   nidx = (const int*)  d_in[5];
    float* out = (float*)d_out;

    int N = in_sizes[0] / CDIM;

    const int SMEM1 = (8192 + 64 * SA_STRIDE) * (int)sizeof(float);        // 66560
    const int SMEMB = 8448 * (int)sizeof(float) + 128 * (int)sizeof(int);  // 34304
    const int SMEM3 = (8192 + 64 * HS_STRIDE) * (int)sizeof(float);        // 50176

    cudaFuncSetAttribute(k1_kernel, cudaFuncAttributeMaxDynamicSharedMemorySize, SMEM1);
    cudaFuncSetAttribute(kb_kernel, cudaFuncAttributeMaxDynamicSharedMemorySize, SMEMB);
    cudaFuncSetAttribute(k3_kernel, cudaFuncAttributeMaxDynamicSharedMemorySize, SMEM3);

    int gridRows = (N + 63) / 64;

    kz_kernel<<<592, 256>>>(N * (HDIM / 4));
    k1_kernel<<<gridRows, 256, SMEM1>>>(x, y, Wa, N);
    ka_kernel<<<dim3((N + 255) / 256, KEEPK), 256>>>(nidx, N);
    kt_kernel<<<1, 256>>>();
    kb_kernel<<<1184, 256, SMEMB>>>(Wb);
    k3_kernel<<<gridRows, 256, SMEM3>>>(Wc, x, out, N);
}